// round 1
// baseline (speedup 1.0000x reference)
#include <cuda_runtime.h>
#include <cstdint>

#define L_LEN 16384
#define CIN   64
#define NB    64
#define NOC   36
#define TILE  256
#define NTHR  128
#define CCH   8          // channels per weight chunk staged in smem

// Packed, zero-padded, duplicated weights: [c][t(0..14)][oc] as float2 {w,w}
__device__ float2 g_w2[CIN * 15 * NOC];
__device__ float  g_bias[NOC];

// ---------------------------------------------------------------------------
// Prep: build padded weight table + bias table. One small block, trivial cost.
// ---------------------------------------------------------------------------
__global__ void prep_kernel(
    const float* __restrict__ w1,  const float* __restrict__ b1,
    const float* __restrict__ w3,  const float* __restrict__ b3,
    const float* __restrict__ w5,  const float* __restrict__ b5,
    const float* __restrict__ w7,  const float* __restrict__ b7,
    const float* __restrict__ w9,  const float* __restrict__ b9,
    const float* __restrict__ w11, const float* __restrict__ b11,
    const float* __restrict__ w13, const float* __restrict__ b13,
    const float* __restrict__ w15, const float* __restrict__ b15)
{
    const float* ws[8] = {w1, w3, w5, w7, w9, w11, w13, w15};
    const float* bs[8] = {b1, b3, b5, b7, b9, b11, b13, b15};
    int tid = threadIdx.x;

    for (int i = tid; i < CIN * 15 * NOC; i += blockDim.x)
        g_w2[i] = make_float2(0.f, 0.f);
    __syncthreads();

    for (int g = 0; g < 8; g++) {
        int k    = 2 * g + 1;
        int cnt  = g ? 5 : 1;
        int oc0  = g ? 1 + 5 * (g - 1) : 0;
        int total = cnt * CIN * k;
        const float* w = ws[g];
        for (int i = tid; i < total; i += blockDim.x) {
            int j  = i % k;
            int c  = (i / k) % CIN;
            int ol = i / (k * CIN);           // i = ((ol*CIN)+c)*k + j, matches (oc,cin,k) row-major
            float v = w[i];
            int t = 7 - g + j;                // center tap at t=7
            g_w2[(c * 15 + t) * NOC + oc0 + ol] = make_float2(v, v);
        }
    }

    if (tid < NOC) {
        int oc = tid;
        int g  = (oc == 0) ? 0 : ((oc - 1) / 5 + 1);
        int ol = (oc == 0) ? 0 : ((oc - 1) % 5);
        g_bias[oc] = bs[g][ol];
    }
}

// ---------------------------------------------------------------------------
// f32x2 helpers (packed dual-fp32 FMA: Blackwell-only, PTX path)
// ---------------------------------------------------------------------------
__device__ __forceinline__ unsigned long long fma2(unsigned long long c,
                                                   unsigned long long a,
                                                   unsigned long long b)
{
    unsigned long long d;
    asm("fma.rn.f32x2 %0, %1, %2, %3;" : "=l"(d) : "l"(a), "l"(b), "l"(c));
    return d;
}

__device__ __forceinline__ unsigned long long pack2(float lo, float hi)
{
    unsigned long long u;
    asm("mov.b64 %0, {%1, %2};" : "=l"(u) : "f"(lo), "f"(hi));
    return u;
}

__device__ __forceinline__ void unpack2(unsigned long long u, float& lo, float& hi)
{
    asm("mov.b64 {%0, %1}, %2;" : "=f"(lo), "=f"(hi) : "l"(u));
}

// oc lower bound active at tap t: tap distance d=|t-7| -> oc >= max(0, 5d-4)
__host__ __device__ constexpr int LO_T(int t)
{
    int d = (t < 7) ? (7 - t) : (t - 7);
    return d ? (5 * d - 4) : 0;
}

// ---------------------------------------------------------------------------
// Main conv kernel.
// Block: (l-tile of 256 positions, batch). 128 threads; thread handles
// positions (l0+tid, l0+tid+128) packed into f32x2 lanes.
// smem: sx[64][142] float2 pre-paired x tile; sw[CCH][15][36] float2 weights.
// ---------------------------------------------------------------------------
#define SX_STRIDE 142
#define SX_ULL    (CIN * SX_STRIDE)          // 9088
#define SW_ULL    (CCH * 15 * NOC)           // 4320
#define SMEM_BYTES ((SX_ULL + SW_ULL) * 8)   // 107264

__global__ void __launch_bounds__(NTHR)
conv_main(const float* __restrict__ x, float* __restrict__ out)
{
    extern __shared__ unsigned long long smem[];
    unsigned long long* sx = smem;            // x tile, as ull (== float2)
    unsigned long long* sw = smem + SX_ULL;   // weight chunk
    float2* sxf = reinterpret_cast<float2*>(sx);
    float2* swf = reinterpret_cast<float2*>(sw);

    const int tid = threadIdx.x;
    const int l0  = blockIdx.x * TILE;
    const int b   = blockIdx.y;
    const float* xb = x + (size_t)b * CIN * L_LEN;

    // Stage x tile, pre-paired: sx[c][q] = { x[l0-7+q], x[l0+121+q] }, q in [0,142)
    for (int i = tid; i < CIN * SX_STRIDE; i += NTHR) {
        int c = i / SX_STRIDE;
        int q = i - c * SX_STRIDE;
        int il = l0 - 7 + q;
        int ih = il + 128;
        float vl = (il >= 0 && il < L_LEN) ? xb[c * L_LEN + il] : 0.f;
        float vh = (ih < L_LEN) ? xb[c * L_LEN + ih] : 0.f;   // ih >= 121 always
        sxf[c * SX_STRIDE + q] = make_float2(vl, vh);
    }

    unsigned long long acc[NOC];
#pragma unroll
    for (int oc = 0; oc < NOC; oc++) {
        float bv = g_bias[oc];
        acc[oc] = pack2(bv, bv);
    }

    for (int c0 = 0; c0 < CIN; c0 += CCH) {
        __syncthreads();     // also covers the initial x-tile stores on iter 0
        const float2* gw = g_w2 + c0 * (15 * NOC);
        for (int i = tid; i < SW_ULL; i += NTHR)
            swf[i] = gw[i];
        __syncthreads();

        for (int c = 0; c < CCH; c++) {
            const unsigned long long* swc = sw + c * (15 * NOC);
            const unsigned long long* sxc = sx + (c0 + c) * SX_STRIDE + tid;
#pragma unroll
            for (int t = 0; t < 15; t++) {
                unsigned long long xv = sxc[t];
                const int lo  = LO_T(t);
                const int lo2 = (lo + 1) & ~1;       // first even oc of the pair loop
                const unsigned long long* wp = swc + t * NOC;
                if (lo & 1)
                    acc[lo] = fma2(acc[lo], xv, wp[lo]);
#pragma unroll
                for (int oc = lo2; oc < NOC; oc += 2) {
                    ulonglong2 wv = *reinterpret_cast<const ulonglong2*>(wp + oc);
                    acc[oc]     = fma2(acc[oc],     xv, wv.x);
                    acc[oc + 1] = fma2(acc[oc + 1], xv, wv.y);
                }
            }
        }
    }

    // Write out: out[b][oc][p0], out[b][oc][p0+128]
    const int p0 = l0 + tid;
#pragma unroll
    for (int oc = 0; oc < NOC; oc++) {
        float flo, fhi;
        unpack2(acc[oc], flo, fhi);
        float* o = out + ((size_t)b * NOC + oc) * L_LEN;
        o[p0]       = flo;
        o[p0 + 128] = fhi;
    }
}

// ---------------------------------------------------------------------------
// Launch
// ---------------------------------------------------------------------------
extern "C" void kernel_launch(void* const* d_in, const int* in_sizes, int n_in,
                              void* d_out, int out_size)
{
    const float* x = (const float*)d_in[0];

    prep_kernel<<<1, 256>>>(
        (const float*)d_in[1],  (const float*)d_in[2],
        (const float*)d_in[3],  (const float*)d_in[4],
        (const float*)d_in[5],  (const float*)d_in[6],
        (const float*)d_in[7],  (const float*)d_in[8],
        (const float*)d_in[9],  (const float*)d_in[10],
        (const float*)d_in[11], (const float*)d_in[12],
        (const float*)d_in[13], (const float*)d_in[14],
        (const float*)d_in[15], (const float*)d_in[16]);

    cudaFuncSetAttribute(conv_main,
                         cudaFuncAttributeMaxDynamicSharedMemorySize,
                         SMEM_BYTES);

    dim3 grid(L_LEN / TILE, NB);
    conv_main<<<grid, NTHR, SMEM_BYTES>>>(x, (float*)d_out);
}

// round 6
// speedup vs baseline: 4.2789x; 4.2789x over previous
#include <cuda_runtime.h>
#include <cuda_fp16.h>
#include <cstdint>

#define L_LEN  16384
#define CIN    64
#define NB     64
#define NOC    36
#define NOCP   40
#define MT     256                 // tile rows (positions)
#define ROWS   270                 // MT + 14 halo
#define NT     (NB * (L_LEN / MT)) // 4096 tiles
#define NTHR   256

// smem layout (bytes)
#define W_OFF       0
#define W_BYTES     76800          // [15 taps][40 oc][64 ch] fp16
#define X0_OFF      76800
#define XBUF_BYTES  34560          // 270 rows * 128 B (64 ch fp16)
#define SMEM_TOTAL  (W_BYTES + 2 * XBUF_BYTES)   // 145920

#define SWZ(o) ((o) ^ (((o) >> 3) & 0x70))

// first active n8-tile per tap (all-cols-inactive tiles skipped)
__device__ constexpr int JMIN[15] = {3,3,2,2,1,0,0,0,0,0,1,2,2,3,3};

__device__ __forceinline__ uint32_t smem_u32(const void* p) {
    uint32_t a;
    asm("{ .reg .u64 t; cvta.to.shared.u64 t, %1; cvt.u32.u64 %0, t; }"
        : "=r"(a) : "l"(p));
    return a;
}

__device__ __forceinline__ void ldsm_x4(uint32_t* r, uint32_t addr) {
    asm volatile("ldmatrix.sync.aligned.m8n8.x4.shared.b16 {%0,%1,%2,%3}, [%4];"
                 : "=r"(r[0]), "=r"(r[1]), "=r"(r[2]), "=r"(r[3]) : "r"(addr));
}
__device__ __forceinline__ void mma16816(float* d, const uint32_t* a, const uint32_t* b) {
    asm volatile(
        "mma.sync.aligned.m16n8k16.row.col.f32.f16.f16.f32 "
        "{%0,%1,%2,%3}, {%4,%5,%6,%7}, {%8,%9}, {%0,%1,%2,%3};"
        : "+f"(d[0]), "+f"(d[1]), "+f"(d[2]), "+f"(d[3])
        : "r"(a[0]), "r"(a[1]), "r"(a[2]), "r"(a[3]), "r"(b[0]), "r"(b[1]));
}

// stage one item (4 channels x 1 row) of the NEXT tile into smem fp16
__device__ __forceinline__ void stage_item(char* dst, const float* xb, int P0, int gi)
{
    if (gi >= 16 * ROWS) return;               // 4320 items
    int q  = gi % ROWS;
    int cq = gi / ROWS;
    int l  = P0 - 7 + q;
    float v0 = 0.f, v1 = 0.f, v2 = 0.f, v3 = 0.f;
    if ((unsigned)l < (unsigned)L_LEN) {
        const float* p = xb + (size_t)cq * 4 * L_LEN + l;
        v0 = __ldg(p);
        v1 = __ldg(p + L_LEN);
        v2 = __ldg(p + 2 * L_LEN);
        v3 = __ldg(p + 3 * L_LEN);
    }
    __half2 h01 = __floats2half2_rn(v0, v1);
    __half2 h23 = __floats2half2_rn(v2, v3);
    uint32_t o = SWZ((uint32_t)(q * 128 + cq * 8));
    uint2 val;
    val.x = *reinterpret_cast<uint32_t*>(&h01);
    val.y = *reinterpret_cast<uint32_t*>(&h23);
    *reinterpret_cast<uint2*>(dst + o) = val;
}

__global__ void __launch_bounds__(NTHR, 1)
conv_hmma(const float* __restrict__ x, float* __restrict__ out,
          const float* __restrict__ w1,  const float* __restrict__ b1,
          const float* __restrict__ w3,  const float* __restrict__ b3,
          const float* __restrict__ w5,  const float* __restrict__ b5,
          const float* __restrict__ w7,  const float* __restrict__ b7,
          const float* __restrict__ w9,  const float* __restrict__ b9,
          const float* __restrict__ w11, const float* __restrict__ b11,
          const float* __restrict__ w13, const float* __restrict__ b13,
          const float* __restrict__ w15, const float* __restrict__ b15)
{
    extern __shared__ char sm[];
    __shared__ float sbias[NOCP];

    const int tid  = threadIdx.x;
    const int lane = tid & 31;
    const int wid  = tid >> 5;
    const int wbase = wid * 32;           // warp covers rows [wbase, wbase+32)
    const int grp  = lane >> 2;
    const int qd   = lane & 3;
    const uint32_t laneRA = lane & 15;           // A ldmatrix row-in-frag
    const uint32_t laneKA = (uint32_t)(lane >> 4) << 4;  // A k-chunk byte
    const uint32_t laneRB = lane & 7;            // B row-in-frag (oc)
    const uint32_t laneKB = (uint32_t)(lane >> 3) << 4;  // B k-chunk byte
    const uint32_t smb = smem_u32(sm);
    const uint32_t wsm = smb + W_OFF;

    // ---- zero W + bias ----
    for (int i = tid; i < W_BYTES / 4; i += NTHR)
        reinterpret_cast<uint32_t*>(sm + W_OFF)[i] = 0u;
    if (tid < NOCP) sbias[tid] = 0.f;
    __syncthreads();

    // ---- fill W (fp16, [t][oc][c], SW128) + bias; stage first tile ----
    {
        const float* ws[8] = {w1, w3, w5, w7, w9, w11, w13, w15};
        const float* bs[8] = {b1, b3, b5, b7, b9, b11, b13, b15};
        for (int g = 0; g < 8; g++) {
            const int k   = 2 * g + 1;
            const int cnt = g ? 5 : 1;
            const int oc0 = g ? (1 + 5 * (g - 1)) : 0;
            const int tot = cnt * CIN * k;
            const float* wg = ws[g];
            for (int i = tid; i < tot; i += NTHR) {
                int j  = i % k;
                int c  = (i / k) % CIN;
                int ol = i / (k * CIN);
                int t  = 7 - g + j;
                uint32_t o = SWZ((uint32_t)((t * NOCP + oc0 + ol) * 128 + c * 2));
                *reinterpret_cast<__half*>(sm + W_OFF + o) = __float2half_rn(wg[i]);
            }
        }
        if (tid < NOC) {
            int oc = tid;
            int g  = oc ? (oc - 1) / 5 + 1 : 0;
            int ol = oc ? (oc - 1) % 5 : 0;
            sbias[oc] = bs[g][ol];
        }
        // first tile -> buffer 0
        const float* xb0 = x + (size_t)(blockIdx.x >> 6) * CIN * L_LEN;
        const int P00 = (blockIdx.x & 63) << 8;
        for (int j2 = 0; j2 < 17; j2++)
            stage_item(sm + X0_OFF, xb0, P00, j2 * NTHR + tid);
    }
    __syncthreads();

    // per-thread bias pairs for the 5 n-tiles
    float bj[5][2];
#pragma unroll
    for (int j = 0; j < 5; j++) {
        bj[j][0] = sbias[8 * j + 2 * qd];
        bj[j][1] = sbias[8 * j + 2 * qd + 1];
    }

    int it = 0;
    for (int tile = blockIdx.x; tile < NT; tile += gridDim.x, it++) {
        const int buf = it & 1;
        const uint32_t xbase = smb + X0_OFF + buf * XBUF_BYTES;
        char* nstage = sm + X0_OFF + (buf ^ 1) * XBUF_BYTES;

        const int ntile = tile + gridDim.x;
        const bool hn = ntile < NT;
        const float* nxb = x + (size_t)(ntile >> 6) * CIN * L_LEN;
        const int nP0 = (ntile & 63) << 8;

        float acc[2][5][4];
#pragma unroll
        for (int mt = 0; mt < 2; mt++)
#pragma unroll
            for (int j = 0; j < 5; j++) {
                acc[mt][j][0] = bj[j][0];
                acc[mt][j][1] = bj[j][1];
                acc[mt][j][2] = bj[j][0];
                acc[mt][j][3] = bj[j][1];
            }

#pragma unroll
        for (int t = 0; t < 15; t++) {
            // interleaved staging of next tile (17 items total over 15 taps)
            if (hn) {
#pragma unroll
                for (int j2 = t; j2 < 17; j2 += 15)
                    stage_item(nstage, nxb, nP0, j2 * NTHR + tid);
            }

            // A fragments: 2 m-tiles x 4 k-tiles
            uint32_t a[2][4][4];
#pragma unroll
            for (int mt = 0; mt < 2; mt++)
#pragma unroll
                for (int kt = 0; kt < 4; kt++) {
                    uint32_t o = (uint32_t)(wbase + mt * 16 + t + laneRA) * 128
                               + (uint32_t)kt * 32 + laneKA;
                    ldsm_x4(a[mt][kt], xbase + SWZ(o));
                }

            const int jm = JMIN[t];
#pragma unroll
            for (int j = 0; j < 5; j++) {
                if (j < jm) continue;
                uint32_t b[8];
                // W is [oc][ch] (K-contiguous) == "col" B operand: NON-trans
                // ldmatrix. r0..r3 = (n8, k0-7 / k8-15 / k16-23 / k24-31).
                uint32_t o = (uint32_t)(t * NOCP + j * 8 + laneRB) * 128 + laneKB;
                ldsm_x4(b,     wsm + SWZ(o));        // k 0..31
                ldsm_x4(b + 4, wsm + SWZ(o + 64));   // k 32..63
#pragma unroll
                for (int kt = 0; kt < 4; kt++)
#pragma unroll
                    for (int mt = 0; mt < 2; mt++)
                        mma16816(acc[mt][j], a[mt][kt], b + 2 * kt);
            }
        }

        // epilogue
        const int b_ = tile >> 6;
        const int P0 = (tile & 63) << 8;
#pragma unroll
        for (int mt = 0; mt < 2; mt++) {
            const int m = P0 + wbase + mt * 16 + grp;
#pragma unroll
            for (int j = 0; j < 5; j++) {
                const int n0 = 8 * j + 2 * qd;
                float* o0 = out + ((size_t)b_ * NOC + n0) * L_LEN + m;
                if (n0 < NOC) {
                    o0[0] = acc[mt][j][0];
                    o0[8] = acc[mt][j][2];
                }
                if (n0 + 1 < NOC) {
                    float* o1 = o0 + L_LEN;
                    o1[0] = acc[mt][j][1];
                    o1[8] = acc[mt][j][3];
                }
            }
        }
        __syncthreads();   // staging of next buffer done; reads of this buffer done
    }
}

extern "C" void kernel_launch(void* const* d_in, const int* in_sizes, int n_in,
                              void* d_out, int out_size)
{
    cudaFuncSetAttribute(conv_hmma, cudaFuncAttributeMaxDynamicSharedMemorySize,
                         SMEM_TOTAL);
    int nsm = 148;
    cudaDeviceGetAttribute(&nsm, cudaDevAttrMultiProcessorCount, 0);
    if (nsm > NT) nsm = NT;

    conv_hmma<<<nsm, NTHR, SMEM_TOTAL>>>(
        (const float*)d_in[0], (float*)d_out,
        (const float*)d_in[1],  (const float*)d_in[2],
        (const float*)d_in[3],  (const float*)d_in[4],
        (const float*)d_in[5],  (const float*)d_in[6],
        (const float*)d_in[7],  (const float*)d_in[8],
        (const float*)d_in[9],  (const float*)d_in[10],
        (const float*)d_in[11], (const float*)d_in[12],
        (const float*)d_in[13], (const float*)d_in[14],
        (const float*)d_in[15], (const float*)d_in[16]);
}